// round 11
// baseline (speedup 1.0000x reference)
#include <cuda_runtime.h>
#include <math.h>

// Problem shape (fixed by reference): 100000 nodes, 1M edges, 256 -> 64 -> 40
#define NMAX 100000
#define EMAX 1000000
constexpr int INC  = 256;
constexpr int HID  = 64;
constexpr int OUTC = 40;

typedef unsigned long long ull;

// Packed f32x2 helpers (B300 FFMA2 — only reachable via PTX fma.rn.f32x2)
__device__ __forceinline__ ull pk2(float lo, float hi) {
    ull r; asm("mov.b64 %0, {%1, %2};" : "=l"(r) : "f"(lo), "f"(hi)); return r;
}
__device__ __forceinline__ void upk2(float& lo, float& hi, ull v) {
    asm("mov.b64 {%0, %1}, %2;" : "=f"(lo), "=f"(hi) : "l"(v));
}
__device__ __forceinline__ ull ffma2(ull a, ull b, ull c) {
    ull d; asm("fma.rn.f32x2 %0, %1, %2, %3;" : "=l"(d) : "l"(a), "l"(b), "l"(c)); return d;
}

// Scratch (static __device__ arrays; no allocation allowed)
__device__ int   d_i64flag;             // 1 if edge_index is int64, 0 if int32
__device__ int   d_cnt [NMAX];          // in-degree (without self loop)
__device__ int   d_excl[NMAX];          // block-local exclusive scan
__device__ int   d_row [NMAX];          // CSR row start
__device__ int   d_cur [NMAX];          // fill cursors
__device__ int   d_part[128];           // scan partials
__device__ int   d_csr [EMAX];          // CSR src indices (grouped by dst)
__device__ float d_dinv[NMAX];
__device__ float d_g1  [(size_t)NMAX * HID];   // RAW x@W1 (no dinv scale)
__device__ float d_h1  [(size_t)NMAX * HID];
__device__ float d_g2  [(size_t)NMAX * OUTC];  // (h1@W2)*dinv
__device__ float d_colsum[OUTC];

// ---------------------------------------------------------------------------
// init + dtype detect fused. Block 0 checks int64 signature (odd words zero).
__global__ void init_kernel(const int* __restrict__ e32, int M) {
    int i = blockIdx.x * blockDim.x + threadIdx.x;
    if (blockIdx.x == 0) {
        __shared__ int nz;
        if (threadIdx.x == 0) nz = 0;
        __syncthreads();
        if (e32[threadIdx.x * 2 + 1] != 0) atomicAdd(&nz, 1);
        __syncthreads();
        if (threadIdx.x == 0) d_i64flag = (nz == 0) ? 1 : 0;
    }
    if (i < M) d_cnt[i] = 0;
    if (i < OUTC) d_colsum[i] = 0.0f;
}

__device__ __forceinline__ int clampi(int v, int M) {
    return min(max(v, 0), M - 1);
}

__global__ void count_kernel(const int* __restrict__ e32, int E, int M) {
    int i = blockIdx.x * blockDim.x + threadIdx.x;
    if (i >= E) return;
    int st = 1 + d_i64flag;                 // element stride in int32 words
    int d = clampi(e32[(E + i) * st], M);   // dst row of edge_index
    atomicAdd(&d_cnt[d], 1);
}

// scan step 1: per-1024-block exclusive scan of d_cnt, block totals to d_part
__global__ void scan1_kernel(int M) {
    __shared__ int ws[32];
    int tid  = threadIdx.x;
    int gid  = blockIdx.x * 1024 + tid;
    int lane = tid & 31, wid = tid >> 5;
    int v = (gid < M) ? d_cnt[gid] : 0;
    int x = v;
    #pragma unroll
    for (int o = 1; o < 32; o <<= 1) {
        int y = __shfl_up_sync(0xffffffffu, x, o);
        if (lane >= o) x += y;
    }
    if (lane == 31) ws[wid] = x;
    __syncthreads();
    if (wid == 0) {
        int s = ws[lane];
        #pragma unroll
        for (int o = 1; o < 32; o <<= 1) {
            int y = __shfl_up_sync(0xffffffffu, s, o);
            if (lane >= o) s += y;
        }
        ws[lane] = s;
    }
    __syncthreads();
    int off = (wid > 0) ? ws[wid - 1] : 0;
    if (gid < M) d_excl[gid] = x - v + off;
    if (tid == 0) d_part[blockIdx.x] = ws[31];
}

// scan step 2: exclusive scan of block partials (np <= 128)
__global__ void scan2_kernel(int np) {
    __shared__ int sp[128];
    int tid = threadIdx.x;
    if (tid < np) sp[tid] = d_part[tid];
    __syncthreads();
    if (tid == 0) {
        int run = 0;
        for (int i = 0; i < np; i++) { int t = sp[i]; sp[i] = run; run += t; }
    }
    __syncthreads();
    if (tid < np) d_part[tid] = sp[tid];
}

// scan step 3: finalize row starts; also dinv and cursor init
__global__ void scan3_kernel(int M) {
    int gid = blockIdx.x * blockDim.x + threadIdx.x;
    if (gid < M) {
        d_row [gid] = d_excl[gid] + d_part[gid >> 10];
        d_cur [gid] = 0;
        d_dinv[gid] = rsqrtf((float)(d_cnt[gid] + 1));   // +1 self loop
    }
}

__global__ void fill_kernel(const int* __restrict__ e32, int E, int M) {
    int i = blockIdx.x * blockDim.x + threadIdx.x;
    if (i >= E) return;
    int st = 1 + d_i64flag;
    int s = clampi(e32[i * st], M);
    int d = clampi(e32[(E + i) * st], M);
    int pos = d_row[d] + atomicAdd(&d_cur[d], 1);
    d_csr[pos] = s;
}

// ---------------------------------------------------------------------------
// GEMM1: g1 = x @ W1 (RAW, no dinv — dinv applied per-edge in agg1)
// M x 256 x 64, BM=64, BK=32, 256 threads, 4x4 micro-tile.
// M-packed FFMA2: A row-pairs loaded directly as f32x2 (no broadcast movs);
// B pre-duplicated (b,b) in smem at tile-fill time.
// Inner loop: 3x LDS.128 + 8x FFMA2 = 11 instr / 16 MACs.
__global__ void gemm1_kernel(const float* __restrict__ x,
                             const float* __restrict__ W1, int M) {
    __shared__ float As [32][68];   // [k][m], 272B rows (16B-aligned)
    __shared__ ull   Bs2[32][64];   // [k][n] duplicated pairs (b,b)
    int tid = threadIdx.x;
    int tx = tid & 15, ty = tid >> 4;
    int row0 = blockIdx.x * 64;
    ull acc[2][4];                  // [row-pair][col], lo=row ty*4+2rp, hi=+1
    #pragma unroll
    for (int rp = 0; rp < 2; rp++)
        #pragma unroll
        for (int c = 0; c < 4; c++) acc[rp][c] = pk2(0.f, 0.f);

    for (int k0 = 0; k0 < INC; k0 += 32) {
        #pragma unroll
        for (int i = 0; i < 2; i++) {
            int idx = tid + i * 256;          // 0..511
            int r = idx >> 3, c4 = idx & 7;   // row 0..63, float4-col 0..7
            int grow = row0 + r;
            float4 v = make_float4(0.f, 0.f, 0.f, 0.f);
            if (grow < M)
                v = *(const float4*)(x + (size_t)grow * INC + k0 + c4 * 4);
            As[c4*4+0][r] = v.x; As[c4*4+1][r] = v.y;
            As[c4*4+2][r] = v.z; As[c4*4+3][r] = v.w;
        }
        #pragma unroll
        for (int i = 0; i < 2; i++) {
            int idx = tid + i * 256;
            int r = idx >> 4, c4 = idx & 15;
            float4 v = *(const float4*)(W1 + (size_t)(k0 + r) * HID + c4 * 4);
            Bs2[r][c4*4+0] = pk2(v.x, v.x);
            Bs2[r][c4*4+1] = pk2(v.y, v.y);
            Bs2[r][c4*4+2] = pk2(v.z, v.z);
            Bs2[r][c4*4+3] = pk2(v.w, v.w);
        }
        __syncthreads();
        #pragma unroll
        for (int k = 0; k < 32; k++) {
            ulonglong2 aq  = *(const ulonglong2*)&As[k][ty*4];     // rows ty*4..+3
            ulonglong2 bq0 = *(const ulonglong2*)&Bs2[k][tx*4];    // cols 0,1 dup
            ulonglong2 bq1 = *(const ulonglong2*)&Bs2[k][tx*4+2];  // cols 2,3 dup
            acc[0][0] = ffma2(aq.x, bq0.x, acc[0][0]);
            acc[0][1] = ffma2(aq.x, bq0.y, acc[0][1]);
            acc[0][2] = ffma2(aq.x, bq1.x, acc[0][2]);
            acc[0][3] = ffma2(aq.x, bq1.y, acc[0][3]);
            acc[1][0] = ffma2(aq.y, bq0.x, acc[1][0]);
            acc[1][1] = ffma2(aq.y, bq0.y, acc[1][1]);
            acc[1][2] = ffma2(aq.y, bq1.x, acc[1][2]);
            acc[1][3] = ffma2(aq.y, bq1.y, acc[1][3]);
        }
        __syncthreads();
    }
    #pragma unroll
    for (int rp = 0; rp < 2; rp++) {
        float l0,h0,l1,h1,l2,h2,l3,h3;
        upk2(l0,h0,acc[rp][0]); upk2(l1,h1,acc[rp][1]);
        upk2(l2,h2,acc[rp][2]); upk2(l3,h3,acc[rp][3]);
        int rlo = row0 + ty*4 + rp*2;
        if (rlo < M)
            *(float4*)(d_g1 + (size_t)rlo * HID + tx * 4) = make_float4(l0,l1,l2,l3);
        if (rlo + 1 < M)
            *(float4*)(d_g1 + (size_t)(rlo+1) * HID + tx * 4) = make_float4(h0,h1,h2,h3);
    }
}

// ---------------------------------------------------------------------------
// Aggregation layer 1 (gather), per-edge dinv[s] scaling:
// h1[d] = relu(dinv[d]*(dinv[d]*g1[d] + sum dinv[s]*g1[s]) + b1)
// 16 threads per node, float4 per thread (64 channels)
__global__ void agg1_kernel(const float* __restrict__ b1, int M) {
    int tid = threadIdx.x;
    int node = blockIdx.x * 16 + (tid >> 4);
    int c4 = tid & 15;
    if (node >= M) return;
    int beg = d_row[node];
    int n   = d_cnt[node];
    float dind = d_dinv[node];
    const float4* g1 = (const float4*)d_g1;
    float4 a = g1[(size_t)node * 16 + c4];   // self loop (scaled by dinv[d])
    float ax = a.x * dind, ay = a.y * dind, az = a.z * dind, aw = a.w * dind;
    int e = 0;
    for (; e + 4 <= n; e += 4) {
        int s0 = d_csr[beg + e + 0], s1 = d_csr[beg + e + 1];
        int s2 = d_csr[beg + e + 2], s3 = d_csr[beg + e + 3];
        float ds0 = d_dinv[s0], ds1 = d_dinv[s1];
        float ds2 = d_dinv[s2], ds3 = d_dinv[s3];
        float4 v0 = g1[(size_t)s0 * 16 + c4];
        float4 v1 = g1[(size_t)s1 * 16 + c4];
        float4 v2 = g1[(size_t)s2 * 16 + c4];
        float4 v3 = g1[(size_t)s3 * 16 + c4];
        ax += v0.x*ds0 + v1.x*ds1 + v2.x*ds2 + v3.x*ds3;
        ay += v0.y*ds0 + v1.y*ds1 + v2.y*ds2 + v3.y*ds3;
        az += v0.z*ds0 + v1.z*ds1 + v2.z*ds2 + v3.z*ds3;
        aw += v0.w*ds0 + v1.w*ds1 + v2.w*ds2 + v3.w*ds3;
    }
    for (; e < n; e++) {
        int s = d_csr[beg + e];
        float ds = d_dinv[s];
        float4 v = g1[(size_t)s * 16 + c4];
        ax += v.x*ds; ay += v.y*ds; az += v.z*ds; aw += v.w*ds;
    }
    float4 kb = *(const float4*)(b1 + c4 * 4);
    float4 h;
    h.x = fmaxf(dind * ax + kb.x, 0.f);
    h.y = fmaxf(dind * ay + kb.y, 0.f);
    h.z = fmaxf(dind * az + kb.z, 0.f);
    h.w = fmaxf(dind * aw + kb.w, 0.f);
    *(float4*)(d_h1 + (size_t)node * HID + c4 * 4) = h;
}

// ---------------------------------------------------------------------------
// GEMM2: g2 = (h1 @ W2) * dinv[row]  (N=40 padded to 64), same FFMA2 scheme
__global__ void gemm2_kernel(const float* __restrict__ W2, int M) {
    __shared__ float As [32][68];
    __shared__ ull   Bs2[32][64];
    int tid = threadIdx.x;
    int tx = tid & 15, ty = tid >> 4;
    int row0 = blockIdx.x * 64;
    ull acc[2][4];
    #pragma unroll
    for (int rp = 0; rp < 2; rp++)
        #pragma unroll
        for (int c = 0; c < 4; c++) acc[rp][c] = pk2(0.f, 0.f);

    for (int k0 = 0; k0 < HID; k0 += 32) {
        #pragma unroll
        for (int i = 0; i < 2; i++) {
            int idx = tid + i * 256;
            int r = idx >> 3, c4 = idx & 7;
            int grow = row0 + r;
            float4 v = make_float4(0.f, 0.f, 0.f, 0.f);
            if (grow < M)
                v = *(const float4*)(d_h1 + (size_t)grow * HID + k0 + c4 * 4);
            As[c4*4+0][r] = v.x; As[c4*4+1][r] = v.y;
            As[c4*4+2][r] = v.z; As[c4*4+3][r] = v.w;
        }
        #pragma unroll
        for (int i = 0; i < 2; i++) {
            int idx = tid + i * 256;
            int r = idx >> 4, c4 = idx & 15;
            float4 v = make_float4(0.f, 0.f, 0.f, 0.f);
            if (c4 < 10)  // 40 valid cols
                v = *(const float4*)(W2 + (size_t)(k0 + r) * OUTC + c4 * 4);
            Bs2[r][c4*4+0] = pk2(v.x, v.x);
            Bs2[r][c4*4+1] = pk2(v.y, v.y);
            Bs2[r][c4*4+2] = pk2(v.z, v.z);
            Bs2[r][c4*4+3] = pk2(v.w, v.w);
        }
        __syncthreads();
        #pragma unroll
        for (int k = 0; k < 32; k++) {
            ulonglong2 aq  = *(const ulonglong2*)&As[k][ty*4];
            ulonglong2 bq0 = *(const ulonglong2*)&Bs2[k][tx*4];
            ulonglong2 bq1 = *(const ulonglong2*)&Bs2[k][tx*4+2];
            acc[0][0] = ffma2(aq.x, bq0.x, acc[0][0]);
            acc[0][1] = ffma2(aq.x, bq0.y, acc[0][1]);
            acc[0][2] = ffma2(aq.x, bq1.x, acc[0][2]);
            acc[0][3] = ffma2(aq.x, bq1.y, acc[0][3]);
            acc[1][0] = ffma2(aq.y, bq0.x, acc[1][0]);
            acc[1][1] = ffma2(aq.y, bq0.y, acc[1][1]);
            acc[1][2] = ffma2(aq.y, bq1.x, acc[1][2]);
            acc[1][3] = ffma2(aq.y, bq1.y, acc[1][3]);
        }
        __syncthreads();
    }
    if (tx < 10) {
        #pragma unroll
        for (int rp = 0; rp < 2; rp++) {
            float l0,h0,l1,h1,l2,h2,l3,h3;
            upk2(l0,h0,acc[rp][0]); upk2(l1,h1,acc[rp][1]);
            upk2(l2,h2,acc[rp][2]); upk2(l3,h3,acc[rp][3]);
            int rlo = row0 + ty*4 + rp*2;
            if (rlo < M) {
                float di = d_dinv[rlo];
                *(float4*)(d_g2 + (size_t)rlo * OUTC + tx * 4) =
                    make_float4(l0*di, l1*di, l2*di, l3*di);
            }
            if (rlo + 1 < M) {
                float di = d_dinv[rlo+1];
                *(float4*)(d_g2 + (size_t)(rlo+1) * OUTC + tx * 4) =
                    make_float4(h0*di, h1*di, h2*di, h3*di);
            }
        }
    }
}

// ---------------------------------------------------------------------------
// Aggregation layer 2 + epilogue: out[d] = dinv[d]*(g2[d] + sum g2[src]) + b2
// (g2 already carries dinv[row]). Accumulates PairNorm column sums.
__global__ void agg2_kernel(const float* __restrict__ b2,
                            float* __restrict__ out, int M) {
    __shared__ float scol[OUTC];
    int tid = threadIdx.x;
    if (tid < OUTC) scol[tid] = 0.0f;
    __syncthreads();
    int node = blockIdx.x * 25 + tid / 10;
    int c4 = tid % 10;
    if (tid < 250 && node < M) {
        int beg = d_row[node];
        int n   = d_cnt[node];
        const float4* g2 = (const float4*)d_g2;
        float4 a = g2[(size_t)node * 10 + c4];
        float ax = a.x, ay = a.y, az = a.z, aw = a.w;
        int e = 0;
        for (; e + 4 <= n; e += 4) {
            int s0 = d_csr[beg + e + 0], s1 = d_csr[beg + e + 1];
            int s2 = d_csr[beg + e + 2], s3 = d_csr[beg + e + 3];
            float4 v0 = g2[(size_t)s0 * 10 + c4];
            float4 v1 = g2[(size_t)s1 * 10 + c4];
            float4 v2 = g2[(size_t)s2 * 10 + c4];
            float4 v3 = g2[(size_t)s3 * 10 + c4];
            ax += v0.x + v1.x + v2.x + v3.x;
            ay += v0.y + v1.y + v2.y + v3.y;
            az += v0.z + v1.z + v2.z + v3.z;
            aw += v0.w + v1.w + v2.w + v3.w;
        }
        for (; e < n; e++) {
            float4 v = g2[(size_t)d_csr[beg + e] * 10 + c4];
            ax += v.x; ay += v.y; az += v.z; aw += v.w;
        }
        float di = d_dinv[node];
        float4 kb = *(const float4*)(b2 + c4 * 4);
        float4 o;
        o.x = di * ax + kb.x; o.y = di * ay + kb.y;
        o.z = di * az + kb.z; o.w = di * aw + kb.w;
        *(float4*)(out + (size_t)node * OUTC + c4 * 4) = o;
        atomicAdd(&scol[c4*4+0], o.x);
        atomicAdd(&scol[c4*4+1], o.y);
        atomicAdd(&scol[c4*4+2], o.z);
        atomicAdd(&scol[c4*4+3], o.w);
    }
    __syncthreads();
    if (tid < OUTC) atomicAdd(&d_colsum[tid], scol[tid]);
}

// ---------------------------------------------------------------------------
__device__ __forceinline__ float warp_sum(float v) {
    #pragma unroll
    for (int o = 16; o > 0; o >>= 1) v += __shfl_xor_sync(0xffffffffu, v, o);
    return v;
}
__device__ __forceinline__ float warp_max(float v) {
    #pragma unroll
    for (int o = 16; o > 0; o >>= 1) v = fmaxf(v, __shfl_xor_sync(0xffffffffu, v, o));
    return v;
}

// PairNorm (PN-SI) + log_softmax, one warp per row
__global__ void final_kernel(float* __restrict__ out, int M, float invN) {
    int gtid = blockIdx.x * blockDim.x + threadIdx.x;
    int row = gtid >> 5, lane = gtid & 31;
    if (row >= M) return;
    int j2 = lane + 32;
    bool h2 = (j2 < OUTC);
    float c0 = out[(size_t)row * OUTC + lane] - d_colsum[lane] * invN;
    float c1 = h2 ? (out[(size_t)row * OUTC + j2] - d_colsum[j2] * invN) : 0.0f;
    float ss = warp_sum(c0 * c0 + c1 * c1);
    float scale = rsqrtf(1e-6f + ss);
    float y0 = c0 * scale;
    float y1 = c1 * scale;
    float m = warp_max(fmaxf(y0, h2 ? y1 : -INFINITY));
    float s = warp_sum(expf(y0 - m) + (h2 ? expf(y1 - m) : 0.0f));
    float lse = m + logf(s);
    out[(size_t)row * OUTC + lane] = y0 - lse;
    if (h2) out[(size_t)row * OUTC + j2] = y1 - lse;
}

// ---------------------------------------------------------------------------
extern "C" void kernel_launch(void* const* d_in, const int* in_sizes, int n_in,
                              void* d_out, int out_size) {
    const float* x  = (const float*)d_in[0];
    const int*   ei = (const int*)d_in[1];   // int32 OR int64 (runtime-detected)
    const float* W1 = (const float*)d_in[2];
    const float* b1 = (const float*)d_in[3];
    const float* W2 = (const float*)d_in[4];
    const float* b2 = (const float*)d_in[5];
    float* out = (float*)d_out;

    int M = in_sizes[0] / INC;     // 100000
    int E = in_sizes[1] / 2;       // 1000000
    const int TB = 256;
    int nscan = (M + 1023) / 1024;

    // Launch order chosen so gemm1 sits at index 3 (the ncu-captured slot).
    init_kernel <<<(M + TB - 1) / TB, TB>>>(ei, M);       // 0
    count_kernel<<<(E + TB - 1) / TB, TB>>>(ei, E, M);    // 1
    scan1_kernel<<<nscan, 1024>>>(M);                     // 2
    gemm1_kernel<<<(M + 63) / 64, 256>>>(x, W1, M);       // 3  <- profiled
    scan2_kernel<<<1, 128>>>(nscan);                      // 4
    scan3_kernel<<<(M + TB - 1) / TB, TB>>>(M);           // 5
    fill_kernel <<<(E + TB - 1) / TB, TB>>>(ei, E, M);    // 6
    agg1_kernel <<<(M + 15) / 16, 256>>>(b1, M);          // 7
    gemm2_kernel<<<(M + 63) / 64, 256>>>(W2, M);          // 8
    agg2_kernel <<<(M + 24) / 25, 256>>>(b2, out, M);     // 9
    final_kernel<<<(M * 32 + TB - 1) / TB, TB>>>(out, M, 1.0f / (float)M); // 10
}

// round 13
// speedup vs baseline: 1.8161x; 1.8161x over previous
#include <cuda_runtime.h>
#include <math.h>

// Problem shape (fixed by reference): 100000 nodes, 1M edges, 256 -> 64 -> 40
#define NMAX 100000
#define EMAX 1000000
constexpr int INC  = 256;
constexpr int HID  = 64;
constexpr int OUTC = 40;

typedef unsigned long long ull;

// Packed f32x2 helpers (B300 FFMA2 — only reachable via PTX fma.rn.f32x2)
__device__ __forceinline__ ull pk2(float lo, float hi) {
    ull r; asm("mov.b64 %0, {%1, %2};" : "=l"(r) : "f"(lo), "f"(hi)); return r;
}
__device__ __forceinline__ void upk2(float& lo, float& hi, ull v) {
    asm("mov.b64 {%0, %1}, %2;" : "=f"(lo), "=f"(hi) : "l"(v));
}
__device__ __forceinline__ ull ffma2(ull a, ull b, ull c) {
    ull d; asm("fma.rn.f32x2 %0, %1, %2, %3;" : "=l"(d) : "l"(a), "l"(b), "l"(c)); return d;
}
__device__ __forceinline__ ull swp2(ull v) {   // (lo,hi) -> (hi,lo)
    ull r;
    asm("{\n\t.reg .b32 l, h;\n\tmov.b64 {l, h}, %1;\n\tmov.b64 %0, {h, l};\n\t}"
        : "=l"(r) : "l"(v));
    return r;
}

// Scratch (static __device__ arrays; no allocation allowed)
__device__ int   d_i64flag;             // 1 if edge_index is int64, 0 if int32
__device__ int   d_cnt [NMAX];          // in-degree (without self loop)
__device__ int   d_excl[NMAX];          // block-local exclusive scan
__device__ int   d_row [NMAX];          // CSR row start
__device__ int   d_cur [NMAX];          // fill cursors
__device__ int   d_part[128];           // scan partials
__device__ int   d_csr [EMAX];          // CSR src indices (grouped by dst)
__device__ float d_dinv[NMAX];
__device__ float d_g1  [(size_t)NMAX * HID];   // RAW x@W1 (no dinv scale)
__device__ float d_h1  [(size_t)NMAX * HID];
__device__ float d_g2  [(size_t)NMAX * OUTC];  // (h1@W2)*dinv
__device__ float d_colsum[OUTC];

// ---------------------------------------------------------------------------
// init + dtype detect fused. Block 0 checks int64 signature (odd words zero).
__global__ void init_kernel(const int* __restrict__ e32, int M) {
    int i = blockIdx.x * blockDim.x + threadIdx.x;
    if (blockIdx.x == 0) {
        __shared__ int nz;
        if (threadIdx.x == 0) nz = 0;
        __syncthreads();
        if (e32[threadIdx.x * 2 + 1] != 0) atomicAdd(&nz, 1);
        __syncthreads();
        if (threadIdx.x == 0) d_i64flag = (nz == 0) ? 1 : 0;
    }
    if (i < M) d_cnt[i] = 0;
    if (i < OUTC) d_colsum[i] = 0.0f;
}

__device__ __forceinline__ int clampi(int v, int M) {
    return min(max(v, 0), M - 1);
}

__global__ void count_kernel(const int* __restrict__ e32, int E, int M) {
    int i = blockIdx.x * blockDim.x + threadIdx.x;
    if (i >= E) return;
    int st = 1 + d_i64flag;                 // element stride in int32 words
    int d = clampi(e32[(E + i) * st], M);   // dst row of edge_index
    atomicAdd(&d_cnt[d], 1);
}

// scan step 1: per-1024-block exclusive scan of d_cnt, block totals to d_part
__global__ void scan1_kernel(int M) {
    __shared__ int ws[32];
    int tid  = threadIdx.x;
    int gid  = blockIdx.x * 1024 + tid;
    int lane = tid & 31, wid = tid >> 5;
    int v = (gid < M) ? d_cnt[gid] : 0;
    int x = v;
    #pragma unroll
    for (int o = 1; o < 32; o <<= 1) {
        int y = __shfl_up_sync(0xffffffffu, x, o);
        if (lane >= o) x += y;
    }
    if (lane == 31) ws[wid] = x;
    __syncthreads();
    if (wid == 0) {
        int s = ws[lane];
        #pragma unroll
        for (int o = 1; o < 32; o <<= 1) {
            int y = __shfl_up_sync(0xffffffffu, s, o);
            if (lane >= o) s += y;
        }
        ws[lane] = s;
    }
    __syncthreads();
    int off = (wid > 0) ? ws[wid - 1] : 0;
    if (gid < M) d_excl[gid] = x - v + off;
    if (tid == 0) d_part[blockIdx.x] = ws[31];
}

// scan step 2: exclusive scan of block partials (np <= 128)
__global__ void scan2_kernel(int np) {
    __shared__ int sp[128];
    int tid = threadIdx.x;
    if (tid < np) sp[tid] = d_part[tid];
    __syncthreads();
    if (tid == 0) {
        int run = 0;
        for (int i = 0; i < np; i++) { int t = sp[i]; sp[i] = run; run += t; }
    }
    __syncthreads();
    if (tid < np) d_part[tid] = sp[tid];
}

// scan step 3: finalize row starts; also dinv and cursor init
__global__ void scan3_kernel(int M) {
    int gid = blockIdx.x * blockDim.x + threadIdx.x;
    if (gid < M) {
        d_row [gid] = d_excl[gid] + d_part[gid >> 10];
        d_cur [gid] = 0;
        d_dinv[gid] = rsqrtf((float)(d_cnt[gid] + 1));   // +1 self loop
    }
}

__global__ void fill_kernel(const int* __restrict__ e32, int E, int M) {
    int i = blockIdx.x * blockDim.x + threadIdx.x;
    if (i >= E) return;
    int st = 1 + d_i64flag;
    int s = clampi(e32[i * st], M);
    int d = clampi(e32[(E + i) * st], M);
    int pos = d_row[d] + atomicAdd(&d_cur[d], 1);
    d_csr[pos] = s;
}

// ---------------------------------------------------------------------------
// GEMM1: g1 = x @ W1 (RAW, no dinv — dinv applied per-edge in agg1)
// BM=128, BN=64, BK=32, 256 threads, 8x4 micro-tile.
// FFMA2 swap-trick: A row-pairs native f32x2, B col-pairs native f32x2,
// straight + crossed FFMA2 cover the 2x2 outer product.
// Inner loop: 3x LDS.128 + 2 swaps + 16 FFMA2 = 0.75 B LDS / MAC.
__global__ void gemm1_kernel(const float* __restrict__ x,
                             const float* __restrict__ W1, int M) {
    __shared__ float As[32][132];   // [k][m]; 528B rows (16B-aligned)
    __shared__ float Bs[32][64];    // [k][n] plain floats
    int tid = threadIdx.x;
    int tx = tid & 15, ty = tid >> 4;
    int row0 = blockIdx.x * 128;
    ull accS[4][2], accX[4][2];     // [row-pair][col-pair] straight / crossed
    #pragma unroll
    for (int p = 0; p < 4; p++) {
        accS[p][0] = 0ull; accS[p][1] = 0ull;
        accX[p][0] = 0ull; accX[p][1] = 0ull;
    }

    for (int k0 = 0; k0 < INC; k0 += 32) {
        #pragma unroll
        for (int i = 0; i < 4; i++) {          // A tile 128x32 = 1024 float4
            int idx = tid + i * 256;
            int r = idx >> 3, c4 = idx & 7;
            int grow = row0 + r;
            float4 v = make_float4(0.f, 0.f, 0.f, 0.f);
            if (grow < M)
                v = *(const float4*)(x + (size_t)grow * INC + k0 + c4 * 4);
            As[c4*4+0][r] = v.x; As[c4*4+1][r] = v.y;
            As[c4*4+2][r] = v.z; As[c4*4+3][r] = v.w;
        }
        #pragma unroll
        for (int i = 0; i < 2; i++) {          // B tile 32x64 = 512 float4
            int idx = tid + i * 256;
            int r = idx >> 4, c4 = idx & 15;
            *(float4*)&Bs[r][c4*4] = *(const float4*)(W1 + (size_t)(k0 + r) * HID + c4 * 4);
        }
        __syncthreads();
        #pragma unroll
        for (int k = 0; k < 32; k++) {
            ulonglong2 a01 = *(const ulonglong2*)&As[k][ty*8];     // rows +0..3
            ulonglong2 a23 = *(const ulonglong2*)&As[k][ty*8+4];   // rows +4..7
            ulonglong2 b   = *(const ulonglong2*)&Bs[k][tx*4];     // cols, 2 pairs
            ull bs0 = swp2(b.x), bs1 = swp2(b.y);
            ull ap0 = a01.x, ap1 = a01.y, ap2 = a23.x, ap3 = a23.y;
            accS[0][0] = ffma2(ap0, b.x, accS[0][0]); accX[0][0] = ffma2(ap0, bs0, accX[0][0]);
            accS[0][1] = ffma2(ap0, b.y, accS[0][1]); accX[0][1] = ffma2(ap0, bs1, accX[0][1]);
            accS[1][0] = ffma2(ap1, b.x, accS[1][0]); accX[1][0] = ffma2(ap1, bs0, accX[1][0]);
            accS[1][1] = ffma2(ap1, b.y, accS[1][1]); accX[1][1] = ffma2(ap1, bs1, accX[1][1]);
            accS[2][0] = ffma2(ap2, b.x, accS[2][0]); accX[2][0] = ffma2(ap2, bs0, accX[2][0]);
            accS[2][1] = ffma2(ap2, b.y, accS[2][1]); accX[2][1] = ffma2(ap2, bs1, accX[2][1]);
            accS[3][0] = ffma2(ap3, b.x, accS[3][0]); accX[3][0] = ffma2(ap3, bs0, accX[3][0]);
            accS[3][1] = ffma2(ap3, b.y, accS[3][1]); accX[3][1] = ffma2(ap3, bs1, accX[3][1]);
        }
        __syncthreads();
    }
    // accS[p][q] = (D[r0][c2q], D[r1][c2q+1]); accX[p][q] = (D[r0][c2q+1], D[r1][c2q])
    #pragma unroll
    for (int p = 0; p < 4; p++) {
        int r0 = row0 + ty * 8 + p * 2;
        float s0l,s0h,x0l,x0h,s1l,s1h,x1l,x1h;
        upk2(s0l, s0h, accS[p][0]); upk2(x0l, x0h, accX[p][0]);
        upk2(s1l, s1h, accS[p][1]); upk2(x1l, x1h, accX[p][1]);
        if (r0 < M)
            *(float4*)(d_g1 + (size_t)r0 * HID + tx * 4) = make_float4(s0l, x0l, s1l, x1l);
        if (r0 + 1 < M)
            *(float4*)(d_g1 + (size_t)(r0+1) * HID + tx * 4) = make_float4(x0h, s0h, x1h, s1h);
    }
}

// ---------------------------------------------------------------------------
// Aggregation layer 1 (gather), per-edge dinv[s] scaling:
// h1[d] = relu(dinv[d]*(dinv[d]*g1[d] + sum dinv[s]*g1[s]) + b1)
// 16 threads per node, float4 per thread (64 channels)
__global__ void agg1_kernel(const float* __restrict__ b1, int M) {
    int tid = threadIdx.x;
    int node = blockIdx.x * 16 + (tid >> 4);
    int c4 = tid & 15;
    if (node >= M) return;
    int beg = d_row[node];
    int n   = d_cnt[node];
    float dind = d_dinv[node];
    const float4* g1 = (const float4*)d_g1;
    float4 a = g1[(size_t)node * 16 + c4];   // self loop (scaled by dinv[d])
    float ax = a.x * dind, ay = a.y * dind, az = a.z * dind, aw = a.w * dind;
    int e = 0;
    for (; e + 4 <= n; e += 4) {
        int s0 = d_csr[beg + e + 0], s1 = d_csr[beg + e + 1];
        int s2 = d_csr[beg + e + 2], s3 = d_csr[beg + e + 3];
        float ds0 = d_dinv[s0], ds1 = d_dinv[s1];
        float ds2 = d_dinv[s2], ds3 = d_dinv[s3];
        float4 v0 = g1[(size_t)s0 * 16 + c4];
        float4 v1 = g1[(size_t)s1 * 16 + c4];
        float4 v2 = g1[(size_t)s2 * 16 + c4];
        float4 v3 = g1[(size_t)s3 * 16 + c4];
        ax += v0.x*ds0 + v1.x*ds1 + v2.x*ds2 + v3.x*ds3;
        ay += v0.y*ds0 + v1.y*ds1 + v2.y*ds2 + v3.y*ds3;
        az += v0.z*ds0 + v1.z*ds1 + v2.z*ds2 + v3.z*ds3;
        aw += v0.w*ds0 + v1.w*ds1 + v2.w*ds2 + v3.w*ds3;
    }
    for (; e < n; e++) {
        int s = d_csr[beg + e];
        float ds = d_dinv[s];
        float4 v = g1[(size_t)s * 16 + c4];
        ax += v.x*ds; ay += v.y*ds; az += v.z*ds; aw += v.w*ds;
    }
    float4 kb = *(const float4*)(b1 + c4 * 4);
    float4 h;
    h.x = fmaxf(dind * ax + kb.x, 0.f);
    h.y = fmaxf(dind * ay + kb.y, 0.f);
    h.z = fmaxf(dind * az + kb.z, 0.f);
    h.w = fmaxf(dind * aw + kb.w, 0.f);
    *(float4*)(d_h1 + (size_t)node * HID + c4 * 4) = h;
}

// ---------------------------------------------------------------------------
// GEMM2: g2 = (h1 @ W2) * dinv[row]  (N=40 padded to 64), same 8x4 FFMA2 scheme
__global__ void gemm2_kernel(const float* __restrict__ W2, int M) {
    __shared__ float As[32][132];
    __shared__ float Bs[32][64];
    int tid = threadIdx.x;
    int tx = tid & 15, ty = tid >> 4;
    int row0 = blockIdx.x * 128;
    ull accS[4][2], accX[4][2];
    #pragma unroll
    for (int p = 0; p < 4; p++) {
        accS[p][0] = 0ull; accS[p][1] = 0ull;
        accX[p][0] = 0ull; accX[p][1] = 0ull;
    }

    for (int k0 = 0; k0 < HID; k0 += 32) {
        #pragma unroll
        for (int i = 0; i < 4; i++) {
            int idx = tid + i * 256;
            int r = idx >> 3, c4 = idx & 7;
            int grow = row0 + r;
            float4 v = make_float4(0.f, 0.f, 0.f, 0.f);
            if (grow < M)
                v = *(const float4*)(d_h1 + (size_t)grow * HID + k0 + c4 * 4);
            As[c4*4+0][r] = v.x; As[c4*4+1][r] = v.y;
            As[c4*4+2][r] = v.z; As[c4*4+3][r] = v.w;
        }
        #pragma unroll
        for (int i = 0; i < 2; i++) {
            int idx = tid + i * 256;
            int r = idx >> 4, c4 = idx & 15;
            float4 v = make_float4(0.f, 0.f, 0.f, 0.f);
            if (c4 < 10)  // 40 valid cols
                v = *(const float4*)(W2 + (size_t)(k0 + r) * OUTC + c4 * 4);
            *(float4*)&Bs[r][c4*4] = v;
        }
        __syncthreads();
        #pragma unroll
        for (int k = 0; k < 32; k++) {
            ulonglong2 a01 = *(const ulonglong2*)&As[k][ty*8];
            ulonglong2 a23 = *(const ulonglong2*)&As[k][ty*8+4];
            ulonglong2 b   = *(const ulonglong2*)&Bs[k][tx*4];
            ull bs0 = swp2(b.x), bs1 = swp2(b.y);
            ull ap0 = a01.x, ap1 = a01.y, ap2 = a23.x, ap3 = a23.y;
            accS[0][0] = ffma2(ap0, b.x, accS[0][0]); accX[0][0] = ffma2(ap0, bs0, accX[0][0]);
            accS[0][1] = ffma2(ap0, b.y, accS[0][1]); accX[0][1] = ffma2(ap0, bs1, accX[0][1]);
            accS[1][0] = ffma2(ap1, b.x, accS[1][0]); accX[1][0] = ffma2(ap1, bs0, accX[1][0]);
            accS[1][1] = ffma2(ap1, b.y, accS[1][1]); accX[1][1] = ffma2(ap1, bs1, accX[1][1]);
            accS[2][0] = ffma2(ap2, b.x, accS[2][0]); accX[2][0] = ffma2(ap2, bs0, accX[2][0]);
            accS[2][1] = ffma2(ap2, b.y, accS[2][1]); accX[2][1] = ffma2(ap2, bs1, accX[2][1]);
            accS[3][0] = ffma2(ap3, b.x, accS[3][0]); accX[3][0] = ffma2(ap3, bs0, accX[3][0]);
            accS[3][1] = ffma2(ap3, b.y, accS[3][1]); accX[3][1] = ffma2(ap3, bs1, accX[3][1]);
        }
        __syncthreads();
    }
    if (tx < 10) {
        #pragma unroll
        for (int p = 0; p < 4; p++) {
            int r0 = row0 + ty * 8 + p * 2;
            float s0l,s0h,x0l,x0h,s1l,s1h,x1l,x1h;
            upk2(s0l, s0h, accS[p][0]); upk2(x0l, x0h, accX[p][0]);
            upk2(s1l, s1h, accS[p][1]); upk2(x1l, x1h, accX[p][1]);
            if (r0 < M) {
                float di = d_dinv[r0];
                *(float4*)(d_g2 + (size_t)r0 * OUTC + tx * 4) =
                    make_float4(s0l*di, x0l*di, s1l*di, x1l*di);
            }
            if (r0 + 1 < M) {
                float di = d_dinv[r0+1];
                *(float4*)(d_g2 + (size_t)(r0+1) * OUTC + tx * 4) =
                    make_float4(x0h*di, s0h*di, x1h*di, s1h*di);
            }
        }
    }
}

// ---------------------------------------------------------------------------
// Aggregation layer 2 + epilogue: out[d] = dinv[d]*(g2[d] + sum g2[src]) + b2
// (g2 already carries dinv[row]). Accumulates PairNorm column sums.
__global__ void agg2_kernel(const float* __restrict__ b2,
                            float* __restrict__ out, int M) {
    __shared__ float scol[OUTC];
    int tid = threadIdx.x;
    if (tid < OUTC) scol[tid] = 0.0f;
    __syncthreads();
    int node = blockIdx.x * 25 + tid / 10;
    int c4 = tid % 10;
    if (tid < 250 && node < M) {
        int beg = d_row[node];
        int n   = d_cnt[node];
        const float4* g2 = (const float4*)d_g2;
        float4 a = g2[(size_t)node * 10 + c4];
        float ax = a.x, ay = a.y, az = a.z, aw = a.w;
        int e = 0;
        for (; e + 4 <= n; e += 4) {
            int s0 = d_csr[beg + e + 0], s1 = d_csr[beg + e + 1];
            int s2 = d_csr[beg + e + 2], s3 = d_csr[beg + e + 3];
            float4 v0 = g2[(size_t)s0 * 10 + c4];
            float4 v1 = g2[(size_t)s1 * 10 + c4];
            float4 v2 = g2[(size_t)s2 * 10 + c4];
            float4 v3 = g2[(size_t)s3 * 10 + c4];
            ax += v0.x + v1.x + v2.x + v3.x;
            ay += v0.y + v1.y + v2.y + v3.y;
            az += v0.z + v1.z + v2.z + v3.z;
            aw += v0.w + v1.w + v2.w + v3.w;
        }
        for (; e < n; e++) {
            float4 v = g2[(size_t)d_csr[beg + e] * 10 + c4];
            ax += v.x; ay += v.y; az += v.z; aw += v.w;
        }
        float di = d_dinv[node];
        float4 kb = *(const float4*)(b2 + c4 * 4);
        float4 o;
        o.x = di * ax + kb.x; o.y = di * ay + kb.y;
        o.z = di * az + kb.z; o.w = di * aw + kb.w;
        *(float4*)(out + (size_t)node * OUTC + c4 * 4) = o;
        atomicAdd(&scol[c4*4+0], o.x);
        atomicAdd(&scol[c4*4+1], o.y);
        atomicAdd(&scol[c4*4+2], o.z);
        atomicAdd(&scol[c4*4+3], o.w);
    }
    __syncthreads();
    if (tid < OUTC) atomicAdd(&d_colsum[tid], scol[tid]);
}

// ---------------------------------------------------------------------------
__device__ __forceinline__ float warp_sum(float v) {
    #pragma unroll
    for (int o = 16; o > 0; o >>= 1) v += __shfl_xor_sync(0xffffffffu, v, o);
    return v;
}
__device__ __forceinline__ float warp_max(float v) {
    #pragma unroll
    for (int o = 16; o > 0; o >>= 1) v = fmaxf(v, __shfl_xor_sync(0xffffffffu, v, o));
    return v;
}

// PairNorm (PN-SI) + log_softmax, one warp per row
__global__ void final_kernel(float* __restrict__ out, int M, float invN) {
    int gtid = blockIdx.x * blockDim.x + threadIdx.x;
    int row = gtid >> 5, lane = gtid & 31;
    if (row >= M) return;
    int j2 = lane + 32;
    bool h2 = (j2 < OUTC);
    float c0 = out[(size_t)row * OUTC + lane] - d_colsum[lane] * invN;
    float c1 = h2 ? (out[(size_t)row * OUTC + j2] - d_colsum[j2] * invN) : 0.0f;
    float ss = warp_sum(c0 * c0 + c1 * c1);
    float scale = rsqrtf(1e-6f + ss);
    float y0 = c0 * scale;
    float y1 = c1 * scale;
    float m = warp_max(fmaxf(y0, h2 ? y1 : -INFINITY));
    float s = warp_sum(expf(y0 - m) + (h2 ? expf(y1 - m) : 0.0f));
    float lse = m + logf(s);
    out[(size_t)row * OUTC + lane] = y0 - lse;
    if (h2) out[(size_t)row * OUTC + j2] = y1 - lse;
}

// ---------------------------------------------------------------------------
extern "C" void kernel_launch(void* const* d_in, const int* in_sizes, int n_in,
                              void* d_out, int out_size) {
    const float* x  = (const float*)d_in[0];
    const int*   ei = (const int*)d_in[1];   // int32 OR int64 (runtime-detected)
    const float* W1 = (const float*)d_in[2];
    const float* b1 = (const float*)d_in[3];
    const float* W2 = (const float*)d_in[4];
    const float* b2 = (const float*)d_in[5];
    float* out = (float*)d_out;

    int M = in_sizes[0] / INC;     // 100000
    int E = in_sizes[1] / 2;       // 1000000
    const int TB = 256;
    int nscan = (M + 1023) / 1024;

    // Launch order chosen so gemm1 sits at index 3 (the ncu-captured slot).
    init_kernel <<<(M + TB - 1) / TB, TB>>>(ei, M);       // 0
    count_kernel<<<(E + TB - 1) / TB, TB>>>(ei, E, M);    // 1
    scan1_kernel<<<nscan, 1024>>>(M);                     // 2
    gemm1_kernel<<<(M + 127) / 128, 256>>>(x, W1, M);     // 3  <- profiled
    scan2_kernel<<<1, 128>>>(nscan);                      // 4
    scan3_kernel<<<(M + TB - 1) / TB, TB>>>(M);           // 5
    fill_kernel <<<(E + TB - 1) / TB, TB>>>(ei, E, M);    // 6
    agg1_kernel <<<(M + 15) / 16, 256>>>(b1, M);          // 7
    gemm2_kernel<<<(M + 127) / 128, 256>>>(W2, M);        // 8
    agg2_kernel <<<(M + 24) / 25, 256>>>(b2, out, M);     // 9
    final_kernel<<<(M * 32 + TB - 1) / TB, TB>>>(out, M, 1.0f / (float)M); // 10
}